// round 15
// baseline (speedup 1.0000x reference)
#include <cuda_runtime.h>

// Problem constants (fixed by dataset)
#define T_IN  60
#define CH    128
#define NPIX  4096
#define HID   128
#define G4    512            // 4*HID
#define RBLK  32             // rows per CTA
#define NCTA  (NPIX / RBLK)  // 128
#define NTH   512            // threads per CTA (16 warps) -- known-good shape
#define KT    32             // K tile
#define PH    36             // hT pitch: every (kk, rg*8) slab 16B-aligned for LDS.128

typedef unsigned long long ull;

// Prepared weights (device globals, ~770KB; allowed)
// GATE-INTERLEAVED layout: [k][col][gate] -- the 4 gate weights for one output
// column are adjacent, so the GEMM reads them with a single LDS.128.
__device__ __align__(16) float g_WtCat[256 * G4];  // k<128 -> W_hh, k>=128 -> W_ih
__device__ __align__(16) float g_WsumT[128 * G4];  // W_ih + W_hh (AR phase)
__device__ __align__(16) float g_bias[G4];         // plain [g] layout

__global__ void prep_kernel(const float* __restrict__ W_ih, const float* __restrict__ W_hh,
                            const float* __restrict__ b_ih, const float* __restrict__ b_hh) {
    int idx = blockIdx.x * blockDim.x + threadIdx.x;
    if (idx < 128 * G4) {
        int k    = idx >> 9;
        int g    = idx & 511;         // original gate-major index: g = gate*128 + col
        int gate = g >> 7;
        int col  = g & 127;
        int dst  = col * 4 + gate;    // interleaved position within the 512-wide row
        float wih = W_ih[g * CH + k];
        float whh = W_hh[g * HID + k];
        g_WtCat[k * G4 + dst]         = whh;
        g_WtCat[(128 + k) * G4 + dst] = wih;
        g_WsumT[k * G4 + dst]         = wih + whh;
    }
    if (idx < G4) g_bias[idx] = b_ih[idx] + b_hh[idx];
}

__device__ __forceinline__ float sigm(float x) {
    return __fdividef(1.0f, 1.0f + __expf(-x));
}
__device__ __forceinline__ float tanh_f(float x) {
    return 2.0f * __fdividef(1.0f, 1.0f + __expf(-2.0f * x)) - 1.0f;
}

// packed f32x2 helpers
__device__ __forceinline__ ull dup2(float v) {
    ull r; asm("mov.b64 %0, {%1, %1};" : "=l"(r) : "f"(v)); return r;
}
#define FFMA2(acc, a, b) asm("fma.rn.f32x2 %0, %1, %2, %0;" : "+l"(acc) : "l"(a), "l"(b))
#define UNPACK2(lo, hi, v) asm("mov.b64 {%0, %1}, %2;" : "=f"(lo), "=f"(hi) : "l"(v))

// cp.async helpers
#define CP_ASYNC16(dst_u32, src_ptr) \
    asm volatile("cp.async.cg.shared.global [%0], [%1], 16;" :: "r"(dst_u32), "l"(src_ptr))
#define CP_COMMIT()   asm volatile("cp.async.commit_group;")
#define CP_WAIT_ALL() asm volatile("cp.async.wait_all;")

// Dynamic smem layout (floats):
//   [0,     4608)  hT   [128][36]  h transposed: hT[k][r] (row pairs)
//   [4608,  8704)  shx  [128][32]  x transposed
//   [8704, 25088)  buf0 [32][512]  weight K-tile (double buffered, interleaved)
//   [25088,41472)  buf1
#define OFF_X  4608
#define OFF_B0 8704
#define OFF_B1 25088
#define SMEM_FLOATS 41472
#define SMEM_BYTES  (SMEM_FLOATS * 4)

extern __shared__ float smem[];

__device__ __forceinline__ void prefetchB(const float* __restrict__ src, float* dst, int tid) {
    unsigned dsh = (unsigned)__cvta_generic_to_shared(dst);
    #pragma unroll
    for (int i = 0; i < 8; ++i) {
        int off = (tid + NTH * i) * 4;        // floats (16B chunks)
        CP_ASYNC16(dsh + off * 4, src + off);
    }
}

__device__ __forceinline__ void prefetchX(const float* __restrict__ image, float* sh_x,
                                          int t, int row_base, int tid) {
    unsigned dsh = (unsigned)__cvta_generic_to_shared(sh_x);
    #pragma unroll
    for (int q = 0; q < 2; ++q) {
        int idx  = tid + NTH * q;             // 0..1023
        int c    = idx >> 3;                  // channel
        int part = idx & 7;                   // 16B chunk of the 32-row stripe
        const float* src = image + ((size_t)t * CH + c) * (size_t)NPIX + row_base + part * 4;
        CP_ASYNC16(dsh + (c * RBLK + part * 4) * 4, src);
    }
}

// one kk step: A slab (4 row-pairs) via 2x LDS.128, B (4 gates, one column)
// via ONE LDS.128 from the gate-interleaved tile, then 4 dup movs.
#define GEMM_KK(APTR)                                                 \
    do {                                                              \
        float4 bv = *(const float4*)(bc + kk * G4 + 4 * jc);          \
        ulonglong2 A01 = *(const ulonglong2*)((APTR) + 0);            \
        ulonglong2 A23 = *(const ulonglong2*)((APTR) + 4);            \
        ull b0 = dup2(bv.x);                                          \
        ull b1 = dup2(bv.y);                                          \
        ull b2 = dup2(bv.z);                                          \
        ull b3 = dup2(bv.w);                                          \
        FFMA2(acc[0][0], A01.x, b0); FFMA2(acc[0][1], A01.x, b1);     \
        FFMA2(acc[0][2], A01.x, b2); FFMA2(acc[0][3], A01.x, b3);     \
        FFMA2(acc[1][0], A01.y, b0); FFMA2(acc[1][1], A01.y, b1);     \
        FFMA2(acc[1][2], A01.y, b2); FFMA2(acc[1][3], A01.y, b3);     \
        FFMA2(acc[2][0], A23.x, b0); FFMA2(acc[2][1], A23.x, b1);     \
        FFMA2(acc[2][2], A23.x, b2); FFMA2(acc[2][3], A23.x, b3);     \
        FFMA2(acc[3][0], A23.y, b0); FFMA2(acc[3][1], A23.y, b1);     \
        FFMA2(acc[3][2], A23.y, b2); FFMA2(acc[3][3], A23.y, b3);     \
    } while (0)

__global__ __launch_bounds__(NTH, 1)
void lstm_persist_kernel(const float* __restrict__ image, float* __restrict__ out, int total_t) {
    float* hT  = smem;
    float* shx = smem + OFF_X;
    float* bufs[2] = { smem + OFF_B0, smem + OFF_B1 };

    const int tid = threadIdx.x;
    const int tx  = tid & 31;
    const int w   = tid >> 5;     // warp 0..15
    const int rg  = w >> 2;       // row group: rows rg*8 .. rg*8+7
    const int cq  = w & 3;        // column quarter
    const int jc  = tx + 32 * cq; // column within each gate block (0..127)
    const int row_base = blockIdx.x * RBLK;

    for (int i = tid; i < 128 * PH; i += NTH) hT[i] = 0.0f;

    // bias and cell state live in registers for the whole run
    ull bias_r[4];
    #pragma unroll
    for (int g = 0; g < 4; ++g) bias_r[g] = dup2(g_bias[jc + 128 * g]);
    float c_lo[4] = {0.f, 0.f, 0.f, 0.f};
    float c_hi[4] = {0.f, 0.f, 0.f, 0.f};

    // prologue: prefetch first weight tile + x(0) (one group)
    prefetchB(g_WtCat, bufs[0], tid);
    prefetchX(image, shx, 0, row_base, tid);
    CP_COMMIT();
    __syncthreads();   // orders hT init

    int par = 0;

    for (int t = 0; t < total_t; ++t) {
        const bool ph1 = (t < T_IN);
        const int  nt  = ph1 ? 8 : 4;

        // accumulators: 4 row-pairs x 4 gate blocks, bias-fused
        ull acc[4][4];
        #pragma unroll
        for (int g = 0; g < 4; ++g) {
            #pragma unroll
            for (int q = 0; q < 4; ++q) acc[q][g] = bias_r[g];
        }

        for (int i = 0; i < nt; ++i) {
            CP_WAIT_ALL();           // tile i arrived (issued one full tile of compute ago)
            __syncthreads();         // all warps done with bufs[par^1]; data visible

            // issue the NEXT prefetch before computing: true overlap
            const bool last_all = (t == total_t - 1) && (i == nt - 1);
            if (!last_all) {
                const float* nB; int nkt;
                if (i + 1 < nt) { nB = ph1 ? g_WtCat : g_WsumT; nkt = (i + 1) * KT; }
                else            { nB = (t + 1 < T_IN) ? g_WtCat : g_WsumT; nkt = 0; }
                prefetchB(nB + (size_t)nkt * G4, bufs[par ^ 1], tid);
                // x(t) staged at tile 0 of step t: the tile-0 barrier guarantees
                // all of step t-1's shx reads finished; arrival forced by tile-1 wait.
                if (ph1 && i == 0 && t > 0)
                    prefetchX(image, shx, t, row_base, tid);
                CP_COMMIT();
            }

            const float* bc = bufs[par];
            const int kt = i * KT;

            if (kt < 128) {
                // A from transposed hidden state hT[k][r]: 16B-aligned slabs (PH=36)
                const float* ab = hT + kt * PH + rg * 8;
                #pragma unroll 8
                for (int kk = 0; kk < KT; ++kk) GEMM_KK(ab + kk * PH);
            } else {
                // A from transposed input tile shx[c][r] (32B-aligned slabs)
                const float* ab = shx + (kt - 128) * RBLK + rg * 8;
                #pragma unroll 8
                for (int kk = 0; kk < KT; ++kk) GEMM_KK(ab + kk * RBLK);
            }
            par ^= 1;
        }

        // AR phase: all tiles read hT -> drain before epilogue overwrites it.
        // Phase1: tiles 4..7 read shx/bufs only; hT reads fenced by their barriers.
        if (!ph1) __syncthreads();

        // epilogue: fully register-resident LSTM cell update
        #pragma unroll
        for (int q = 0; q < 4; ++q) {
            float i0, i1, f0, f1, g0, g1, o0, o1;
            UNPACK2(i0, i1, acc[q][0]);
            UNPACK2(f0, f1, acc[q][1]);
            UNPACK2(g0, g1, acc[q][2]);
            UNPACK2(o0, o1, acc[q][3]);
            int r0 = rg * 8 + 2 * q;
            float cn0 = sigm(f0) * c_lo[q] + sigm(i0) * tanh_f(g0);
            float cn1 = sigm(f1) * c_hi[q] + sigm(i1) * tanh_f(g1);
            c_lo[q] = cn0;
            c_hi[q] = cn1;
            float hn0 = sigm(o0) * tanh_f(cn0);
            float hn1 = sigm(o1) * tanh_f(cn1);
            *(float2*)(hT + jc * PH + r0) = make_float2(hn0, hn1);
            out[((size_t)(row_base + r0)     * total_t + t) * HID + jc] = hn0;
            out[((size_t)(row_base + r0 + 1) * total_t + t) * HID + jc] = hn1;
        }
        // next step's tile-0 top __syncthreads orders hT writes vs GEMM reads
    }
}

extern "C" void kernel_launch(void* const* d_in, const int* in_sizes, int n_in,
                              void* d_out, int out_size) {
    const float* image = (const float*)d_in[0];
    // d_in[1] = mask (unused by reference forward)
    const float* W_ih  = (const float*)d_in[2];
    const float* W_hh  = (const float*)d_in[3];
    const float* b_ih  = (const float*)d_in[4];
    const float* b_hh  = (const float*)d_in[5];
    float* out = (float*)d_out;

    int total_t = out_size / (NPIX * HID);   // 114

    prep_kernel<<<(128 * G4 + 255) / 256, 256>>>(W_ih, W_hh, b_ih, b_hh);

    cudaFuncSetAttribute(lstm_persist_kernel,
                         cudaFuncAttributeMaxDynamicSharedMemorySize, SMEM_BYTES);
    lstm_persist_kernel<<<NCTA, NTH, SMEM_BYTES>>>(image, out, total_t);
}

// round 16
// speedup vs baseline: 1.7714x; 1.7714x over previous
#include <cuda_runtime.h>

// Problem constants (fixed by dataset)
#define T_IN  60
#define CH    128
#define NPIX  4096
#define HID   128
#define G4    512            // 4*HID
#define RBLK  32             // rows per CTA (two independent groups of 16)
#define NCTA  (NPIX / RBLK)  // 128
#define NTH   512            // threads per CTA
#define GRP   256            // threads per group (8 warps)
#define GROWS 16             // rows per group
#define KT    32             // K tile
#define PH2   20             // group hT pitch: (kk*20 + rg*8)*4B is 16B-aligned

typedef unsigned long long ull;

// Prepared weights (device globals, ~770KB; allowed). Gate-major layout (R13).
__device__ __align__(16) float g_WtCat[256 * G4];  // [k][g]: k<128 -> W_hh, k>=128 -> W_ih
__device__ __align__(16) float g_WsumT[128 * G4];  // [k][g]: W_ih + W_hh (AR phase)
__device__ __align__(16) float g_bias[G4];

__global__ void prep_kernel(const float* __restrict__ W_ih, const float* __restrict__ W_hh,
                            const float* __restrict__ b_ih, const float* __restrict__ b_hh) {
    int idx = blockIdx.x * blockDim.x + threadIdx.x;
    if (idx < 128 * G4) {
        int k = idx >> 9;
        int g = idx & 511;
        float wih = W_ih[g * CH + k];
        float whh = W_hh[g * HID + k];
        g_WtCat[k * G4 + g]         = whh;
        g_WtCat[(128 + k) * G4 + g] = wih;
        g_WsumT[k * G4 + g]         = wih + whh;
    }
    if (idx < G4) g_bias[idx] = b_ih[idx] + b_hh[idx];
}

__device__ __forceinline__ float sigm(float x) {
    return __fdividef(1.0f, 1.0f + __expf(-x));
}
__device__ __forceinline__ float tanh_f(float x) {
    return 2.0f * __fdividef(1.0f, 1.0f + __expf(-2.0f * x)) - 1.0f;
}

// packed f32x2 helpers
__device__ __forceinline__ ull dup2(float v) {
    ull r; asm("mov.b64 %0, {%1, %1};" : "=l"(r) : "f"(v)); return r;
}
#define FFMA2(acc, a, b) asm("fma.rn.f32x2 %0, %1, %2, %0;" : "+l"(acc) : "l"(a), "l"(b))
#define UNPACK2(lo, hi, v) asm("mov.b64 {%0, %1}, %2;" : "=f"(lo), "=f"(hi) : "l"(v))

// cp.async helpers
#define CP_ASYNC16(dst_u32, src_ptr) \
    asm volatile("cp.async.cg.shared.global [%0], [%1], 16;" :: "r"(dst_u32), "l"(src_ptr))
#define CP_COMMIT()   asm volatile("cp.async.commit_group;")
#define CP_WAIT_ALL() asm volatile("cp.async.wait_all;")

// group-scoped named barrier (group 0 -> id 1, group 1 -> id 2)
#define BARG(id) asm volatile("bar.sync %0, %1;" :: "r"(id), "r"(GRP) : "memory")

// Per-group smem layout (floats), group g at offset g*GS:
//   [0,    2560)  hTg  [128][20]  group's h transposed (16 rows + 4 pad)
//   [2560, 4608)  shxg [128][16]  group's x transposed
//   [4608,20992)  bufg [32][512]  weight K-tile (single buffer)
#define OFF_XG 2560
#define OFF_BG 4608
#define GS     20992
#define SMEM_FLOATS (2 * GS)
#define SMEM_BYTES  (SMEM_FLOATS * 4)   // 167,936 B

extern __shared__ float smem[];

__device__ __forceinline__ void prefetchB(const float* __restrict__ src, float* dst, int gtid) {
    unsigned dsh = (unsigned)__cvta_generic_to_shared(dst);
    #pragma unroll
    for (int i = 0; i < 16; ++i) {
        int off = (gtid + GRP * i) * 4;       // floats (16B chunks), 64KB total
        CP_ASYNC16(dsh + off * 4, src + off);
    }
}

__device__ __forceinline__ void prefetchX(const float* __restrict__ image, float* shxg,
                                          int t, int row0, int gtid) {
    unsigned dsh = (unsigned)__cvta_generic_to_shared(shxg);
    #pragma unroll
    for (int q = 0; q < 2; ++q) {
        int idx  = gtid + GRP * q;            // 0..511
        int c    = idx >> 2;                  // channel
        int part = idx & 3;                   // 16B chunk of the 16-row stripe
        const float* src = image + ((size_t)t * CH + c) * (size_t)NPIX + row0 + part * 4;
        CP_ASYNC16(dsh + (c * GROWS + part * 4) * 4, src);
    }
}

// one kk step (R13-identical register profile): A slab via 2x LDS.128,
// B via 4 scalar gate-major LDS + dup movs.
#define GEMM_KK(APTR)                                                 \
    do {                                                              \
        const float* br = bc + kk * G4 + jc;                          \
        ulonglong2 A01 = *(const ulonglong2*)((APTR) + 0);            \
        ulonglong2 A23 = *(const ulonglong2*)((APTR) + 4);            \
        ull b0 = dup2(br[0]);                                         \
        ull b1 = dup2(br[128]);                                       \
        ull b2 = dup2(br[256]);                                       \
        ull b3 = dup2(br[384]);                                       \
        FFMA2(acc[0][0], A01.x, b0); FFMA2(acc[0][1], A01.x, b1);     \
        FFMA2(acc[0][2], A01.x, b2); FFMA2(acc[0][3], A01.x, b3);     \
        FFMA2(acc[1][0], A01.y, b0); FFMA2(acc[1][1], A01.y, b1);     \
        FFMA2(acc[1][2], A01.y, b2); FFMA2(acc[1][3], A01.y, b3);     \
        FFMA2(acc[2][0], A23.x, b0); FFMA2(acc[2][1], A23.x, b1);     \
        FFMA2(acc[2][2], A23.x, b2); FFMA2(acc[2][3], A23.x, b3);     \
        FFMA2(acc[3][0], A23.y, b0); FFMA2(acc[3][1], A23.y, b1);     \
        FFMA2(acc[3][2], A23.y, b2); FFMA2(acc[3][3], A23.y, b3);     \
    } while (0)

__global__ __launch_bounds__(NTH, 1)
void lstm_persist_kernel(const float* __restrict__ image, float* __restrict__ out, int total_t) {
    const int tid  = threadIdx.x;
    const int g    = tid >> 8;       // group 0 or 1
    const int gtid = tid & 255;
    const int tx   = gtid & 31;
    const int w    = gtid >> 5;      // warp-in-group 0..7
    const int rg   = w >> 2;         // row group within the 16 rows: 0 or 1
    const int cq   = w & 3;
    const int jc   = tx + 32 * cq;   // column within each gate block (0..127)
    const int bid  = 1 + g;          // named barrier id for this group
    const int row0 = blockIdx.x * RBLK + g * GROWS;

    float* hTg  = smem + g * GS;
    float* shxg = hTg + OFF_XG;
    float* bufg = hTg + OFF_BG;

    for (int i = gtid; i < 128 * PH2; i += GRP) hTg[i] = 0.0f;

    // bias and cell state in registers for the whole run
    ull bias_r[4];
    #pragma unroll
    for (int gg = 0; gg < 4; ++gg) bias_r[gg] = dup2(g_bias[jc + 128 * gg]);
    float c_lo[4] = {0.f, 0.f, 0.f, 0.f};
    float c_hi[4] = {0.f, 0.f, 0.f, 0.f};

    // prologue: stage tile 0 + x(0); group-local wait + barrier
    prefetchB(g_WtCat, bufg, gtid);
    prefetchX(image, shxg, 0, row0, gtid);
    CP_COMMIT();
    CP_WAIT_ALL();
    BARG(bid);    // tile0/x0 visible; hTg zeros ordered

    for (int t = 0; t < total_t; ++t) {
        const bool ph1 = (t < T_IN);
        const int  nt  = ph1 ? 8 : 4;

        // accumulators: 4 row-pairs x 4 gate blocks, bias-fused
        ull acc[4][4];
        #pragma unroll
        for (int gg = 0; gg < 4; ++gg) {
            #pragma unroll
            for (int q = 0; q < 4; ++q) acc[q][gg] = bias_r[gg];
        }

        for (int i = 0; i < nt; ++i) {
            const float* bc = bufg;
            const int kt = i * KT;

            if (kt < 128) {
                // A from group's transposed hidden state hTg[k][r]
                const float* ab = hTg + kt * PH2 + rg * 8;
                #pragma unroll 8
                for (int kk = 0; kk < KT; ++kk) GEMM_KK(ab + kk * PH2);
            } else {
                // A from group's transposed input tile shxg[c][r]
                const float* ab = shxg + (kt - 128) * GROWS + rg * 8;
                #pragma unroll 8
                for (int kk = 0; kk < KT; ++kk) GEMM_KK(ab + kk * GROWS);
            }

            BARG(bid);   // whole group done reading bufg (and, at i==nt-1, hTg/shxg)

            // stage the next tile into the single buffer (group-local pipeline;
            // the partner group's compute covers this exposed load)
            const bool last_all = (t == total_t - 1) && (i == nt - 1);
            if (!last_all) {
                int t2, i2;
                if (i + 1 < nt) { t2 = t; i2 = i + 1; }
                else            { t2 = t + 1; i2 = 0; }
                const float* nB = ((t2 < T_IN) ? g_WtCat : g_WsumT) + (size_t)(i2 * KT) * G4;
                prefetchB(nB, bufg, gtid);
                if (i == nt - 1 && t2 < T_IN)        // x(t+1); all x(t) reads done
                    prefetchX(image, shxg, t2, row0, gtid);
                CP_COMMIT();
            }

            if (i == nt - 1) {
                // epilogue overlapped with the in-flight step-boundary load:
                // fully register-resident LSTM cell update for this group's rows
                #pragma unroll
                for (int q = 0; q < 4; ++q) {
                    float i0, i1, f0, f1, g0, g1, o0, o1;
                    UNPACK2(i0, i1, acc[q][0]);
                    UNPACK2(f0, f1, acc[q][1]);
                    UNPACK2(g0, g1, acc[q][2]);
                    UNPACK2(o0, o1, acc[q][3]);
                    int r0 = rg * 8 + 2 * q;
                    float cn0 = sigm(f0) * c_lo[q] + sigm(i0) * tanh_f(g0);
                    float cn1 = sigm(f1) * c_hi[q] + sigm(i1) * tanh_f(g1);
                    c_lo[q] = cn0;
                    c_hi[q] = cn1;
                    float hn0 = sigm(o0) * tanh_f(cn0);
                    float hn1 = sigm(o1) * tanh_f(cn1);
                    *(float2*)(hTg + jc * PH2 + r0) = make_float2(hn0, hn1);
                    out[((size_t)(row0 + r0)     * total_t + t) * HID + jc] = hn0;
                    out[((size_t)(row0 + r0 + 1) * total_t + t) * HID + jc] = hn1;
                }
            }

            CP_WAIT_ALL();
            BARG(bid);   // refilled buffer (and epilogue hTg writes) visible to group
        }
    }
}

extern "C" void kernel_launch(void* const* d_in, const int* in_sizes, int n_in,
                              void* d_out, int out_size) {
    const float* image = (const float*)d_in[0];
    // d_in[1] = mask (unused by reference forward)
    const float* W_ih  = (const float*)d_in[2];
    const float* W_hh  = (const float*)d_in[3];
    const float* b_ih  = (const float*)d_in[4];
    const float* b_hh  = (const float*)d_in[5];
    float* out = (float*)d_out;

    int total_t = out_size / (NPIX * HID);   // 114

    prep_kernel<<<(128 * G4 + 255) / 256, 256>>>(W_ih, W_hh, b_ih, b_hh);

    cudaFuncSetAttribute(lstm_persist_kernel,
                         cudaFuncAttributeMaxDynamicSharedMemorySize, SMEM_BYTES);
    lstm_persist_kernel<<<NCTA, NTH, SMEM_BYTES>>>(image, out, total_t);
}